// round 14
// baseline (speedup 1.0000x reference)
#include <cuda_runtime.h>
#include <math.h>

#define BATCH 20
#define MVIS 262144
#define CDIV(a,b) (((a)+(b)-1)/(b))
#define RBN 0.99950037f   // 1/sqrt(1.001)
#define PI_F 3.14159265358979f

// ---------------- static device scratch ----------------
static __device__ float2 g_grids[2*BATCH*512*512];   // gA = +0, gB = +BATCH*512*512 (contiguous)
static __device__ float2 g_m0  [BATCH*MVIS];
static __device__ float2 g_m1  [BATCH*MVIS];
static __device__ float2 g_sub0[BATCH*MVIS];
static __device__ float  g_cin [BATCH*2*256*256];
static __device__ float  g_h1  [BATCH*16*256*256];
static __device__ float  g_xc  [BATCH*128*128];
static __device__ float  g_q0  [BATCH*256*256];
static __device__ float  g_q1  [BATCH*128*128];
static __device__ float  g_q2  [BATCH*64*64];

__device__ __forceinline__ float2 cmulf(float2 a, float2 b){
  return make_float2(fmaf(a.x,b.x,-a.y*b.y), fmaf(a.x,b.y,a.y*b.x));
}
__device__ __forceinline__ float2 f2add(float2 a, float2 b){ return make_float2(a.x+b.x, a.y+b.y); }
__device__ __forceinline__ float2 f2sub(float2 a, float2 b){ return make_float2(a.x-b.x, a.y-b.y); }
__device__ __forceinline__ constexpr int IX(int i){ return i + (i>>4); }

__device__ __forceinline__ void tw_sincos(float x, float* s, float* c){
  __sincosf(x * PI_F, s, c);
}

__device__ __forceinline__ void red2(float2* p, float x, float y){
  asm volatile("red.global.add.v2.f32 [%0], {%1, %2};" :: "l"(p), "f"(x), "f"(y) : "memory");
}

// ---- cp.async helpers ----
__device__ __forceinline__ void cpa4(void* smem_dst, const float* gsrc){
  unsigned sa = (unsigned)__cvta_generic_to_shared(smem_dst);
  asm volatile("cp.async.ca.shared.global [%0], [%1], 4;" :: "r"(sa), "l"(gsrc));
}
__device__ __forceinline__ void cpa_commit(){ asm volatile("cp.async.commit_group;"); }
template<int NN>
__device__ __forceinline__ void cpa_wait(){ asm volatile("cp.async.wait_group %0;" :: "n"(NN)); }

// ---- packed f32x2 helpers ----
__device__ __forceinline__ unsigned long long pack2(float lo, float hi){
  unsigned long long r;
  asm("mov.b64 %0, {%1, %2};" : "=l"(r) : "r"(__float_as_uint(lo)), "r"(__float_as_uint(hi)));
  return r;
}
__device__ __forceinline__ unsigned long long dup2(float v){
  unsigned long long r;
  asm("mov.b64 %0, {%1, %1};" : "=l"(r) : "r"(__float_as_uint(v)));
  return r;
}
__device__ __forceinline__ void fma2(unsigned long long &d, unsigned long long a,
                                     unsigned long long b, unsigned long long c){
  asm("fma.rn.f32x2 %0, %1, %2, %3;" : "=l"(d) : "l"(a), "l"(b), "l"(c));
}
__device__ __forceinline__ float2 unpack2(unsigned long long v){
  unsigned lo, hi;
  asm("mov.b64 {%0, %1}, %2;" : "=r"(lo), "=r"(hi) : "l"(v));
  return make_float2(__uint_as_float(lo), __uint_as_float(hi));
}

// ---------------- radix-8 building blocks ----------------
template<bool INV>
__device__ __forceinline__ void dft4v(float2 x0, float2 x1, float2 x2, float2 x3,
                                      float2&y0, float2&y1, float2&y2, float2&y3){
  float2 t0=f2add(x0,x2), t1=f2sub(x0,x2), t2=f2add(x1,x3), t3=f2sub(x1,x3);
  float2 j3 = INV ? make_float2(-t3.y,t3.x) : make_float2(t3.y,-t3.x);
  y0=f2add(t0,t2); y2=f2sub(t0,t2); y1=f2add(t1,j3); y3=f2sub(t1,j3);
}

template<bool INV>
__device__ __forceinline__ void dft8v(const float2* a, float2* b){
  float2 e0,e1,e2,e3,o0,o1,o2,o3;
  dft4v<INV>(a[0],a[2],a[4],a[6],e0,e1,e2,e3);
  dft4v<INV>(a[1],a[3],a[5],a[7],o0,o1,o2,o3);
  const float C8 = 0.7071067811865476f;
  float2 p1 = INV ? cmulf(o1, make_float2(C8,C8))   : cmulf(o1, make_float2(C8,-C8));
  float2 p2 = INV ? make_float2(-o2.y,o2.x)         : make_float2(o2.y,-o2.x);
  float2 p3 = INV ? cmulf(o3, make_float2(-C8,C8))  : cmulf(o3, make_float2(-C8,-C8));
  b[0]=f2add(e0,o0); b[4]=f2sub(e0,o0);
  b[1]=f2add(e1,p1); b[5]=f2sub(e1,p1);
  b[2]=f2add(e2,p2); b[6]=f2sub(e2,p2);
  b[3]=f2add(e3,p3); b[7]=f2sub(e3,p3);
}

template<bool INV, int NS>
__device__ __forceinline__ void tw8(int jm, float2* w){
  float sn,cs; tw_sincos(((INV?2.f:-2.f)*jm)/(8*NS), &sn, &cs);
  w[0]=make_float2(cs,sn);
  w[1]=cmulf(w[0],w[0]);
  w[2]=cmulf(w[1],w[0]);
  w[3]=cmulf(w[1],w[1]);
  w[4]=cmulf(w[3],w[0]);
  w[5]=cmulf(w[2],w[2]);
  w[6]=cmulf(w[3],w[2]);
}

// ---- in-place stages (read -> sync -> write -> sync) ----
template<bool INV, int N, int NS>
__device__ __forceinline__ void row_r8_ip(float2* buf, int t){
  constexpr int T = N/8;
  const int jm = t & (NS-1);
  float2 a[8];
  #pragma unroll
  for (int k=0;k<8;k++) a[k]=buf[IX(t+k*T)];
  __syncthreads();
  if (NS>1){
    float2 w[7]; tw8<INV,NS>(jm,w);
    #pragma unroll
    for (int k=1;k<8;k++) a[k]=cmulf(a[k],w[k-1]);
  }
  float2 b[8]; dft8v<INV>(a,b);
  const int d=((t-jm)<<3)+jm;
  #pragma unroll
  for (int k=0;k<8;k++) buf[IX(d+k*NS)]=b[k];
  __syncthreads();
}
template<bool INV, int N>
__device__ __forceinline__ void row_r4_tail_ip(float2* buf, int t){
  constexpr int T=N/8;
  float2 v[2][4];
  #pragma unroll
  for (int q=0;q<2;q++){
    int j=t+q*T;
    v[q][0]=buf[IX(j)];       v[q][1]=buf[IX(j+N/4)];
    v[q][2]=buf[IX(j+N/2)];   v[q][3]=buf[IX(j+3*(N/4))];
  }
  __syncthreads();
  #pragma unroll
  for (int q=0;q<2;q++){
    int j=t+q*T;
    float sn,cs; tw_sincos(((INV?2.f:-2.f)*j)/N,&sn,&cs);
    float2 w1=make_float2(cs,sn),w2=cmulf(w1,w1),w3=cmulf(w2,w1);
    float2 y0,y1,y2,y3;
    dft4v<INV>(v[q][0],cmulf(v[q][1],w1),cmulf(v[q][2],w2),cmulf(v[q][3],w3),y0,y1,y2,y3);
    buf[IX(j)]=y0; buf[IX(j+N/4)]=y1; buf[IX(j+N/2)]=y2; buf[IX(j+3*(N/4))]=y3;
  }
  __syncthreads();
}
template<bool INV, int N>
__device__ __forceinline__ void row_r2_tail_ip(float2* buf, int t){
  constexpr int T=N/8;
  float2 v0[4], v1[4];
  #pragma unroll
  for (int q=0;q<4;q++){
    int j=t+q*T;
    v0[q]=buf[IX(j)]; v1[q]=buf[IX(j+N/2)];
  }
  __syncthreads();
  #pragma unroll
  for (int q=0;q<4;q++){
    int j=t+q*T;
    float sn,cs; tw_sincos(((INV?2.f:-2.f)*j)/N,&sn,&cs);
    float2 vw=cmulf(v1[q],make_float2(cs,sn));
    buf[IX(j)]    =f2add(v0[q],vw);
    buf[IX(j+N/2)]=f2sub(v0[q],vw);
  }
  __syncthreads();
}

// ---------------- row kernels (single smem buffer) ----------------
template<int N, bool INV, int R>
__global__ void fft8_rows(float2* __restrict__ ga, float2* __restrict__ gb){
  constexpr int T = N/8;
  constexpr int PAD = N + N/16 + 2;
  __shared__ float2 sh[R][PAD];
  const int t = threadIdx.x, rr = threadIdx.y;
  float2* g = blockIdx.z ? gb : ga;
  float2* base = g + ((size_t)blockIdx.y * N + blockIdx.x*R + rr) * N;
  float2* buf = sh[rr];
  {
    float2 a[8], b[8];
    #pragma unroll
    for (int k=0;k<8;k++) a[k]=base[t+k*T];
    dft8v<INV>(a,b);
    const int d=t<<3;
    #pragma unroll
    for (int k=0;k<8;k++) buf[IX(d+k)]=b[k];
  }
  __syncthreads();
  row_r8_ip<INV,N,8>(buf,t);
  if (N==512)      row_r8_ip<INV,N,64>(buf,t);
  else if (N==256) row_r4_tail_ip<INV,N>(buf,t);
  else             row_r2_tail_ip<INV,N>(buf,t);
  const float sc = INV ? 1.0f/N : 1.0f;
  #pragma unroll
  for (int k=0;k<8;k++){
    float2 v = buf[IX(t+k*T)];
    base[t+k*T] = make_float2(v.x*sc, v.y*sc);
  }
}

// DIR row pass from compact real (N/2 x N/2), zero-padded. Writes grid rows < N/2.
template<int N, int R>
__global__ void fft8_rows_dir_real(float2* __restrict__ g, const float* __restrict__ xr){
  constexpr int T = N/8;
  constexpr int PAD = N + N/16 + 2;
  __shared__ float2 sh[R][PAD];
  const int t = threadIdx.x, rr = threadIdx.y;
  const int y = blockIdx.x*R + rr, b = blockIdx.y;
  const float* row = xr + ((size_t)b*(N/2) + y)*(N/2);
  float2* base = g + ((size_t)b * N + y) * N;
  float2* buf = sh[rr];
  {
    float2 a[8], bb[8];
    #pragma unroll
    for (int k=0;k<4;k++) a[k]=make_float2(row[t+k*T],0.f);
    #pragma unroll
    for (int k=4;k<8;k++) a[k]=make_float2(0.f,0.f);
    dft8v<false>(a,bb);
    const int d=t<<3;
    #pragma unroll
    for (int k=0;k<8;k++) buf[IX(d+k)]=bb[k];
  }
  __syncthreads();
  row_r8_ip<false,N,8>(buf,t);
  if (N==512)      row_r8_ip<false,N,64>(buf,t);
  else if (N==256) row_r4_tail_ip<false,N>(buf,t);
  else             row_r2_tail_ip<false,N>(buf,t);
  #pragma unroll
  for (int k=0;k<8;k++) base[t+k*T] = buf[IX(t+k*T)];
}

// ---------------- column kernels (single buffer, one column per thread) ------
template<bool INV, int N, int NS, int PAD>
__device__ __forceinline__ void col_r8_ip(float2 (*sh)[PAD], int t, int cc){
  constexpr int T = N/8;
  const int jm = t & (NS-1);
  float2 a[8];
  #pragma unroll
  for (int k=0;k<8;k++) a[k]=sh[cc][IX(t+k*T)];
  __syncthreads();
  if (NS>1){
    float2 w[7]; tw8<INV,NS>(jm,w);
    #pragma unroll
    for (int k=1;k<8;k++) a[k]=cmulf(a[k],w[k-1]);
  }
  float2 b[8]; dft8v<INV>(a,b);
  const int d=((t-jm)<<3)+jm;
  #pragma unroll
  for (int k=0;k<8;k++) sh[cc][IX(d+k*NS)]=b[k];
  __syncthreads();
}
template<bool INV, int N, int PAD>
__device__ __forceinline__ void col_r4_tail_ip(float2 (*sh)[PAD], int t, int cc){
  constexpr int T=N/8;
  float2 v[2][4];
  #pragma unroll
  for (int q=0;q<2;q++){
    int j=t+q*T;
    v[q][0]=sh[cc][IX(j)];       v[q][1]=sh[cc][IX(j+N/4)];
    v[q][2]=sh[cc][IX(j+N/2)];   v[q][3]=sh[cc][IX(j+3*(N/4))];
  }
  __syncthreads();
  #pragma unroll
  for (int q=0;q<2;q++){
    int j=t+q*T;
    float sn,cs; tw_sincos(((INV?2.f:-2.f)*j)/N,&sn,&cs);
    float2 w1=make_float2(cs,sn),w2=cmulf(w1,w1),w3=cmulf(w2,w1);
    float2 y0,y1,y2,y3;
    dft4v<INV>(v[q][0],cmulf(v[q][1],w1),cmulf(v[q][2],w2),cmulf(v[q][3],w3),y0,y1,y2,y3);
    sh[cc][IX(j)]=y0; sh[cc][IX(j+N/4)]=y1; sh[cc][IX(j+N/2)]=y2; sh[cc][IX(j+3*(N/4))]=y3;
  }
  __syncthreads();
}
template<bool INV, int N, int PAD>
__device__ __forceinline__ void col_r2_tail_ip(float2 (*sh)[PAD], int t, int cc){
  constexpr int T=N/8;
  float2 v0[4], v1[4];
  #pragma unroll
  for (int q=0;q<4;q++){
    int j=t+q*T;
    v0[q]=sh[cc][IX(j)]; v1[q]=sh[cc][IX(j+N/2)];
  }
  __syncthreads();
  #pragma unroll
  for (int q=0;q<4;q++){
    int j=t+q*T;
    float sn,cs; tw_sincos(((INV?2.f:-2.f)*j)/N,&sn,&cs);
    float2 vw=cmulf(v1[q],make_float2(cs,sn));
    sh[cc][IX(j)]    =f2add(v0[q],vw);
    sh[cc][IX(j+N/2)]=f2sub(v0[q],vw);
  }
  __syncthreads();
}

// ADJ col pass (inverse), pruned cols<N/2; Re of rows<N/2 to compact buffer.
template<int N, int TC>
__global__ void fft8_cols_adj_real(const float2* __restrict__ ga, float* __restrict__ da,
                                   const float2* __restrict__ gb, float* __restrict__ db2,
                                   int imgStride){
  constexpr int PAD = N + N/16 + 2;
  constexpr int T = N/8;
  constexpr int NT = T*TC;
  __shared__ float2 sh[TC][PAD];
  const int t = threadIdx.x, cc = threadIdx.y;
  const int tid = cc*T + t;
  const float2* g = blockIdx.z ? gb : ga;
  float* dstp = blockIdx.z ? db2 : da;
  const float2* base = g + (size_t)blockIdx.y * N * N + blockIdx.x * TC;
  float* db = dstp + (size_t)blockIdx.y * imgStride + blockIdx.x * TC;
  for (int i=tid; i<N*TC; i+=NT){
    int r=i/TC, c2=i&(TC-1);
    sh[c2][IX(r)] = base[(size_t)r*N + c2];
  }
  __syncthreads();
  col_r8_ip<true,N,1,PAD>(sh,t,cc);
  col_r8_ip<true,N,8,PAD>(sh,t,cc);
  if (N==512)      col_r8_ip<true,N,64,PAD>(sh,t,cc);
  else if (N==256) col_r4_tail_ip<true,N,PAD>(sh,t,cc);
  else             col_r2_tail_ip<true,N,PAD>(sh,t,cc);
  const float sc = 1.0f/N;
  for (int i=tid; i<(N/2)*TC; i+=NT){
    int r=i/TC, c2=i&(TC-1);
    db[(size_t)r*(N/2) + c2] = sh[c2][IX(r)].x * sc;
  }
}

// DIR col pass (forward): loads only rows < N/2 (rest zero via stage0), full store.
template<int N, int TC>
__global__ void fft8_cols_dir(float2* __restrict__ g){
  constexpr int PAD = N + N/16 + 2;
  constexpr int T = N/8;
  constexpr int NT = T*TC;
  __shared__ float2 sh[TC][PAD];
  const int t = threadIdx.x, cc = threadIdx.y;
  const int tid = cc*T + t;
  float2* base = g + (size_t)blockIdx.y * N * N + blockIdx.x * TC;
  for (int i=tid; i<(N/2)*TC; i+=NT){
    int r=i/TC, c2=i&(TC-1);
    sh[c2][IX(r)] = base[(size_t)r*N + c2];
  }
  __syncthreads();
  {
    float2 a[8], b[8];
    #pragma unroll
    for (int k=0;k<4;k++) a[k]=sh[cc][IX(t+k*T)];
    #pragma unroll
    for (int k=4;k<8;k++) a[k]=make_float2(0.f,0.f);
    __syncthreads();
    dft8v<false>(a,b);
    const int d=t<<3;
    #pragma unroll
    for (int k=0;k<8;k++) sh[cc][IX(d+k)]=b[k];
  }
  __syncthreads();
  col_r8_ip<false,N,8,PAD>(sh,t,cc);
  if (N==512)      col_r8_ip<false,N,64,PAD>(sh,t,cc);
  else if (N==256) col_r4_tail_ip<false,N,PAD>(sh,t,cc);
  else             col_r2_tail_ip<false,N,PAD>(sh,t,cc);
  for (int i=tid; i<N*TC; i+=NT){
    int r=i/TC, c2=i&(TC-1);
    base[(size_t)r*N + c2] = sh[c2][IX(r)];
  }
}

// ---------------- NUFFT pieces ----------------
__global__ void k_scatter_vis(float2* __restrict__ grid, const float* __restrict__ vr,
                              const float* __restrict__ vi, const float* __restrict__ w,
                              const int* __restrict__ idx){
  int i = blockIdx.x*blockDim.x+threadIdx.x;
  if (i >= BATCH*MVIS) return;
  int b=i/MVIS, k=i-b*MVIS;
  float wv=w[k];
  red2(&grid[b*512*512+idx[k]], vr[i]*wv, vi[i]*wv);
}

__global__ void k_gather_m0(const float2* __restrict__ grid, const int* __restrict__ idx,
                            const float* __restrict__ w, float2* __restrict__ m0,
                            float2* __restrict__ sub0){
  int i = blockIdx.x*blockDim.x+threadIdx.x;
  if (i >= BATCH*MVIS) return;
  int b=i/MVIS, k=i-b*MVIS;
  float2 v = grid[b*512*512+idx[k]];
  m0[i]=v; float wv=w[k];
  sub0[i]=make_float2(v.x*wv, v.y*wv);
}

__global__ void k_scatter_sel(float2* __restrict__ grid, const float2* __restrict__ src,
                              const int* __restrict__ sel, const int* __restrict__ idx,
                              int n, int srcStride, int gridSize){
  int i = blockIdx.x*blockDim.x+threadIdx.x;
  if (i >= BATCH*n) return;
  int b=i/n, j=i-b*n;
  float2 v = src[(size_t)b*srcStride + sel[j]];
  red2(&grid[b*gridSize + idx[j]], v.x, v.y);
}

__global__ void k_gather(const float2* __restrict__ grid, const int* __restrict__ idx,
                         float2* __restrict__ dst, int n, int dstStride, int gridSize){
  int i = blockIdx.x*blockDim.x+threadIdx.x;
  if (i >= BATCH*n) return;
  int b=i/n, j=i-b*n;
  dst[(size_t)b*dstStride + j] = grid[b*gridSize + idx[j]];
}

__global__ void k_set_sel(float2* __restrict__ dstVec, const int* __restrict__ sel,
                          const float2* __restrict__ grid, const int* __restrict__ idx,
                          int n, int dstStride, int gridSize){
  int i = blockIdx.x*blockDim.x+threadIdx.x;
  if (i >= BATCH*n) return;
  int b=i/n, j=i-b*n;
  dstVec[(size_t)b*dstStride + sel[j]] = grid[b*gridSize + idx[j]];
}

__global__ void k_scatterE(float2* __restrict__ gA, float2* __restrict__ gB,
                           const float2* __restrict__ m1, const float2* __restrict__ sub0,
                           const int* __restrict__ sel1, const int* __restrict__ idx1, int n1){
  int i = blockIdx.x*blockDim.x+threadIdx.x;
  if (i >= BATCH*n1) return;
  int b=i/n1, j=i-b*n1;
  float2 v = m1[(size_t)b*n1 + j];
  float2 s = sub0[(size_t)b*MVIS + sel1[j]];
  int gi = b*65536 + idx1[j];
  red2(&gA[gi], v.x, v.y);
  red2(&gB[gi], v.x-s.x, v.y-s.y);
}

__global__ void k_scatterG(float2* __restrict__ gA, float2* __restrict__ gB,
                           const float2* __restrict__ m0, const float2* __restrict__ sub0,
                           const int* __restrict__ idx0){
  int i = blockIdx.x*blockDim.x+threadIdx.x;
  if (i >= BATCH*MVIS) return;
  int b=i/MVIS, k=i-b*MVIS;
  float2 v=m0[i], s=sub0[i];
  int gi = b*262144 + idx0[k];
  red2(&gA[gi], v.x, v.y);
  red2(&gB[gi], v.x-s.x, v.y-s.y);
}

// ---------------- conv block (packed f32x2) ----------------
template<int F, int H>
__global__ void __launch_bounds__(256) conv1_k(
    const float* __restrict__ cin, const float* __restrict__ W1,
    const float* __restrict__ b1, const float* __restrict__ g1,
    const float* __restrict__ be1, float* __restrict__ h1){
  __shared__ float si[2][18][18];
  __shared__ float sw[18*F];
  __shared__ float sb[F], sg[F], sbe[F];
  const int tx=threadIdx.x, ty=threadIdx.y, tid=ty*16+tx;
  const int b=blockIdx.z, x0=blockIdx.x*16, y0=blockIdx.y*16;
  for (int i=tid; i<18*F; i+=256) sw[i]=W1[i];
  for (int i=tid; i<F; i+=256){ sb[i]=b1[i]; sg[i]=g1[i]*RBN; sbe[i]=be1[i]; }
  const float* cb = cin + (size_t)b*2*H*H;
  for (int c=0;c<2;c++)
    for (int i=tid;i<18*18;i+=256){
      int yy=i/18, xx=i-yy*18;
      int gy=y0+yy-1, gx=x0+xx-1;
      si[c][yy][xx] = (gy>=0&&gy<H&&gx>=0&&gx<H) ? cb[c*H*H + gy*H + gx] : 0.f;
    }
  __syncthreads();
  unsigned long long acc2[F/2];
  #pragma unroll
  for (int o2=0;o2<F/2;o2++) acc2[o2]=pack2(sb[2*o2], sb[2*o2+1]);
  #pragma unroll
  for (int ky=0;ky<3;ky++)
    #pragma unroll
    for (int kx=0;kx<3;kx++)
      #pragma unroll
      for (int c=0;c<2;c++){
        unsigned long long vv = dup2(si[c][ty+ky][tx+kx]);
        const float* wt = sw + ((ky*3+kx)*2+c)*F;
        #pragma unroll
        for (int o2=0;o2<F/2;o2++)
          fma2(acc2[o2], vv, *reinterpret_cast<const unsigned long long*>(wt + 2*o2), acc2[o2]);
      }
  const int y=y0+ty, x=x0+tx;
  float* hb = h1 + (size_t)b*F*H*H + (size_t)y*H + x;
  #pragma unroll
  for (int o2=0;o2<F/2;o2++){
    float2 a = unpack2(acc2[o2]);
    hb[(size_t)(2*o2  )*H*H] = fmaf(fmaxf(a.x,0.f), sg[2*o2  ], sbe[2*o2  ]);
    hb[(size_t)(2*o2+1)*H*H] = fmaf(fmaxf(a.y,0.f), sg[2*o2+1], sbe[2*o2+1]);
  }
}

// conv2 (3x3 F->F, relu, bn) fused with conv3 (1x1 F->1) + sigmoid.
// Double-buffered cp.async input tile prefetch across the ic loop.
template<int F, int H>
__global__ void __launch_bounds__(256) conv23_k(
    const float* __restrict__ h1, const float* __restrict__ W2,
    const float* __restrict__ b2, const float* __restrict__ g2,
    const float* __restrict__ be2, const float* __restrict__ W3,
    const float* __restrict__ b3, float* __restrict__ out){
  __shared__ float sw[9*F*F];
  __shared__ float tile[2][18][18];
  __shared__ float sb[F], sg[F], sbe[F], sw3[F];
  const int tx=threadIdx.x, ty=threadIdx.y, tid=ty*16+tx;
  const int b=blockIdx.z, x0=blockIdx.x*16, y0=blockIdx.y*16;
  for (int i=tid; i<9*F*F; i+=256){
    int oc=i%F, r=i/F, tap=r%9, ic=r/9;
    sw[i] = W2[(tap*F+ic)*F+oc];
  }
  for (int i=tid; i<F; i+=256){ sb[i]=b2[i]; sg[i]=g2[i]*RBN; sbe[i]=be2[i]; sw3[i]=W3[i]; }
  const float* hb = h1 + (size_t)b*F*H*H;

  auto load_tile = [&](int ic, int bufi){
    const float* src = hb + (size_t)ic*H*H;
    for (int i=tid;i<18*18;i+=256){
      int yy=i/18, xx=i-yy*18;
      int gy=y0+yy-1, gx=x0+xx-1;
      if (gy>=0&&gy<H&&gx>=0&&gx<H) cpa4(&tile[bufi][yy][xx], src + gy*H + gx);
      else                          tile[bufi][yy][xx]=0.f;
    }
    cpa_commit();
  };

  load_tile(0,0);
  __syncthreads();   // covers sw/sb tables too

  unsigned long long acc2[F/2];
  #pragma unroll
  for (int o2=0;o2<F/2;o2++) acc2[o2]=pack2(sb[2*o2], sb[2*o2+1]);

  for (int ic=0; ic<F; ic++){
    const int cur = ic&1;
    if (ic+1<F){ load_tile(ic+1, cur^1); cpa_wait<1>(); }
    else       { cpa_wait<0>(); }
    __syncthreads();
    const float* wi = sw + ic*9*F;
    #pragma unroll
    for (int ky=0;ky<3;ky++)
      #pragma unroll
      for (int kx=0;kx<3;kx++){
        unsigned long long vv = dup2(tile[cur][ty+ky][tx+kx]);
        const float* wt = wi + (ky*3+kx)*F;
        #pragma unroll
        for (int o2=0;o2<F/2;o2++)
          fma2(acc2[o2], vv, *reinterpret_cast<const unsigned long long*>(wt + 2*o2), acc2[o2]);
      }
    __syncthreads();
  }
  float s = b3[0];
  #pragma unroll
  for (int o2=0;o2<F/2;o2++){
    float2 a = unpack2(acc2[o2]);
    s = fmaf(fmaf(fmaxf(a.x,0.f), sg[2*o2  ], sbe[2*o2  ]), sw3[2*o2  ], s);
    s = fmaf(fmaf(fmaxf(a.y,0.f), sg[2*o2+1], sbe[2*o2+1]), sw3[2*o2+1], s);
  }
  out[(size_t)b*H*H + (size_t)(y0+ty)*H + (x0+tx)] = 1.f/(1.f+__expf(-s));
}

// ---------------- launch ----------------
extern "C" void kernel_launch(void* const* d_in, const int* in_sizes, int n_in,
                              void* d_out, int out_size){
  const float* vr = (const float*)d_in[0];
  const float* vi = (const float*)d_in[1];
  const float* w  = (const float*)d_in[2];
  const float *c0w1=(const float*)d_in[3],  *c0b1=(const float*)d_in[4],
              *c0g1=(const float*)d_in[5],  *c0be1=(const float*)d_in[6],
              *c0w2=(const float*)d_in[7],  *c0b2=(const float*)d_in[8],
              *c0g2=(const float*)d_in[9],  *c0be2=(const float*)d_in[10],
              *c0w3=(const float*)d_in[11], *c0b3=(const float*)d_in[12];
  const float *c1w1=(const float*)d_in[13], *c1b1=(const float*)d_in[14],
              *c1g1=(const float*)d_in[15], *c1be1=(const float*)d_in[16],
              *c1w2=(const float*)d_in[17], *c1b2=(const float*)d_in[18],
              *c1g2=(const float*)d_in[19], *c1be2=(const float*)d_in[20],
              *c1w3=(const float*)d_in[21], *c1b3=(const float*)d_in[22];
  const int* idx0=(const int*)d_in[23];
  const int* idx1=(const int*)d_in[24];
  const int* idx2=(const int*)d_in[25];
  const int* sel1=(const int*)d_in[26];
  const int* sel2=(const int*)d_in[27];
  const int n1 = in_sizes[24], n2 = in_sizes[25];
  float* out = (float*)d_out;

  float2 *gA,*gB,*m0,*m1,*sub0; float *cin,*h1,*xc,*q0,*q1,*q2;
  cudaGetSymbolAddress((void**)&gA,   g_grids);
  gB = gA + (size_t)BATCH*512*512;
  cudaGetSymbolAddress((void**)&m0,   g_m0);
  cudaGetSymbolAddress((void**)&m1,   g_m1);
  cudaGetSymbolAddress((void**)&sub0, g_sub0);
  cudaGetSymbolAddress((void**)&cin,  g_cin);
  cudaGetSymbolAddress((void**)&h1,   g_h1);
  cudaGetSymbolAddress((void**)&xc,   g_xc);
  cudaGetSymbolAddress((void**)&q0,   g_q0);
  cudaGetSymbolAddress((void**)&q1,   g_q1);
  cudaGetSymbolAddress((void**)&q2,   g_q2);

  const int TPB=256;
  // A: adj0 of vis*w -> q0 (256x256 real quadrant)
  cudaMemsetAsync(gA, 0, (size_t)BATCH*262144*sizeof(float2), 0);
  k_scatter_vis<<<CDIV(BATCH*MVIS,TPB),TPB>>>(gA, vr, vi, w, idx0);
  fft8_rows<512,true,4><<<dim3(128,BATCH,1),dim3(64,4)>>>(gA, gA);
  fft8_cols_adj_real<512,4><<<dim3(64,BATCH,1),dim3(64,4)>>>(gA, q0, gA, q0, 256*256);
  // B: dir0 from q0 -> m0, sub0
  fft8_rows_dir_real<512,4><<<dim3(64,BATCH),dim3(64,4)>>>(gA, q0);
  fft8_cols_dir<512,4><<<dim3(128,BATCH),dim3(64,4)>>>(gA);
  k_gather_m0<<<CDIV(BATCH*MVIS,TPB),TPB>>>(gA, idx0, w, m0, sub0);
  // C: adj1 of m0[sel1] -> q1 (128x128)
  cudaMemsetAsync(gB, 0, (size_t)BATCH*65536*sizeof(float2), 0);
  k_scatter_sel<<<CDIV(BATCH*n1,TPB),TPB>>>(gB, m0, sel1, idx1, n1, MVIS, 65536);
  fft8_rows<256,true,8><<<dim3(32,BATCH,1),dim3(32,8)>>>(gB, gB);
  fft8_cols_adj_real<256,8><<<dim3(16,BATCH,1),dim3(32,8)>>>(gB, q1, gB, q1, 128*128);
  // D: dir1 from q1 -> m1
  fft8_rows_dir_real<256,8><<<dim3(16,BATCH),dim3(32,8)>>>(gB, q1);
  fft8_cols_dir<256,8><<<dim3(32,BATCH),dim3(32,8)>>>(gB);
  k_gather<<<CDIV(BATCH*n1,TPB),TPB>>>(gB, idx1, m1, n1, n1, 65536);
  // E: adj2 of m1[sel2] -> q2 (64x64)
  cudaMemsetAsync(gA, 0, (size_t)BATCH*16384*sizeof(float2), 0);
  k_scatter_sel<<<CDIV(BATCH*n2,TPB),TPB>>>(gA, m1, sel2, idx2, n2, n1, 16384);
  fft8_rows<128,true,16><<<dim3(8,BATCH,1),dim3(16,16)>>>(gA, gA);
  fft8_cols_adj_real<128,8><<<dim3(8,BATCH,1),dim3(16,8)>>>(gA, q2, gA, q2, 64*64);
  // F: dir2 from q2 -> meas; m1 becomes full1
  fft8_rows_dir_real<128,16><<<dim3(4,BATCH),dim3(16,16)>>>(gA, q2);
  fft8_cols_dir<128,8><<<dim3(16,BATCH),dim3(16,8)>>>(gA);
  k_set_sel<<<CDIV(BATCH*n2,TPB),TPB>>>(m1, sel2, gA, idx2, n2, n1, 16384);
  // G: two adj1 (full1, full1 - sub1) -> cin channels directly (merged via z)
  cudaMemsetAsync(gA, 0, (size_t)BATCH*65536*sizeof(float2), 0);
  cudaMemsetAsync(gB, 0, (size_t)BATCH*65536*sizeof(float2), 0);
  k_scatterE<<<CDIV(BATCH*n1,TPB),TPB>>>(gA, gB, m1, sub0, sel1, idx1, n1);
  fft8_rows<256,true,8><<<dim3(32,BATCH,2),dim3(32,8)>>>(gA, gB);
  fft8_cols_adj_real<256,8><<<dim3(16,BATCH,2),dim3(32,8)>>>(gA, cin, gB, cin + 128*128, 2*128*128);
  // H: conv block p0 (F=32 @128) -> xc
  conv1_k <32,128><<<dim3(8,8,BATCH),dim3(16,16)>>>(cin, c0w1, c0b1, c0g1, c0be1, h1);
  conv23_k<32,128><<<dim3(8,8,BATCH),dim3(16,16)>>>(h1, c0w2, c0b2, c0g2, c0be2, c0w3, c0b3, xc);
  // I: dir1 of xc; m0 becomes full0
  fft8_rows_dir_real<256,8><<<dim3(16,BATCH),dim3(32,8)>>>(gA, xc);
  fft8_cols_dir<256,8><<<dim3(32,BATCH),dim3(32,8)>>>(gA);
  k_set_sel<<<CDIV(BATCH*n1,TPB),TPB>>>(m0, sel1, gA, idx1, n1, MVIS, 65536);
  // J: two adj0 (full0, full0 - sub0) -> cin (gA,gB contiguous: one memset)
  cudaMemsetAsync(gA, 0, (size_t)2*BATCH*262144*sizeof(float2), 0);
  k_scatterG<<<CDIV(BATCH*MVIS,TPB),TPB>>>(gA, gB, m0, sub0, idx0);
  fft8_rows<512,true,4><<<dim3(128,BATCH,2),dim3(64,4)>>>(gA, gB);
  fft8_cols_adj_real<512,4><<<dim3(64,BATCH,2),dim3(64,4)>>>(gA, cin, gB, cin + 256*256, 2*256*256);
  // K: conv block p1 (F=16 @256) -> out
  conv1_k <16,256><<<dim3(16,16,BATCH),dim3(16,16)>>>(cin, c1w1, c1b1, c1g1, c1be1, h1);
  conv23_k<16,256><<<dim3(16,16,BATCH),dim3(16,16)>>>(h1, c1w2, c1b2, c1g2, c1be2, c1w3, c1b3, out);
}

// round 15
// speedup vs baseline: 1.0583x; 1.0583x over previous
#include <cuda_runtime.h>
#include <math.h>

#define BATCH 20
#define MVIS 262144
#define CDIV(a,b) (((a)+(b)-1)/(b))
#define RBN 0.99950037f   // 1/sqrt(1.001)
#define PI_F 3.14159265358979f

// ---------------- static device scratch ----------------
static __device__ float2 g_grids[2*BATCH*512*512];   // gA = +0, gB = +BATCH*512*512
static __device__ float2 g_m0  [BATCH*MVIS];
static __device__ float2 g_m1  [BATCH*MVIS];
static __device__ float2 g_sub0[BATCH*MVIS];
static __device__ float  g_cin [BATCH*2*256*256];
static __device__ float  g_xc  [BATCH*128*128];
static __device__ float  g_q0  [BATCH*256*256];
static __device__ float  g_q1  [BATCH*128*128];
static __device__ float  g_q2  [BATCH*64*64];

__device__ __forceinline__ float2 cmulf(float2 a, float2 b){
  return make_float2(fmaf(a.x,b.x,-a.y*b.y), fmaf(a.x,b.y,a.y*b.x));
}
__device__ __forceinline__ float2 f2add(float2 a, float2 b){ return make_float2(a.x+b.x, a.y+b.y); }
__device__ __forceinline__ float2 f2sub(float2 a, float2 b){ return make_float2(a.x-b.x, a.y-b.y); }
__device__ __forceinline__ constexpr int IX(int i){ return i + (i>>4); }

__device__ __forceinline__ void tw_sincos(float x, float* s, float* c){
  __sincosf(x * PI_F, s, c);
}

__device__ __forceinline__ void red2(float2* p, float x, float y){
  asm volatile("red.global.add.v2.f32 [%0], {%1, %2};" :: "l"(p), "f"(x), "f"(y) : "memory");
}

// ---- packed f32x2 helpers ----
__device__ __forceinline__ unsigned long long pack2(float lo, float hi){
  unsigned long long r;
  asm("mov.b64 %0, {%1, %2};" : "=l"(r) : "r"(__float_as_uint(lo)), "r"(__float_as_uint(hi)));
  return r;
}
__device__ __forceinline__ unsigned long long dup2(float v){
  unsigned long long r;
  asm("mov.b64 %0, {%1, %1};" : "=l"(r) : "r"(__float_as_uint(v)));
  return r;
}
__device__ __forceinline__ void fma2(unsigned long long &d, unsigned long long a,
                                     unsigned long long b, unsigned long long c){
  asm("fma.rn.f32x2 %0, %1, %2, %3;" : "=l"(d) : "l"(a), "l"(b), "l"(c));
}
__device__ __forceinline__ float2 unpack2(unsigned long long v){
  unsigned lo, hi;
  asm("mov.b64 {%0, %1}, %2;" : "=r"(lo), "=r"(hi) : "l"(v));
  return make_float2(__uint_as_float(lo), __uint_as_float(hi));
}

// ---------------- radix-8 building blocks ----------------
template<bool INV>
__device__ __forceinline__ void dft4v(float2 x0, float2 x1, float2 x2, float2 x3,
                                      float2&y0, float2&y1, float2&y2, float2&y3){
  float2 t0=f2add(x0,x2), t1=f2sub(x0,x2), t2=f2add(x1,x3), t3=f2sub(x1,x3);
  float2 j3 = INV ? make_float2(-t3.y,t3.x) : make_float2(t3.y,-t3.x);
  y0=f2add(t0,t2); y2=f2sub(t0,t2); y1=f2add(t1,j3); y3=f2sub(t1,j3);
}

template<bool INV>
__device__ __forceinline__ void dft8v(const float2* a, float2* b){
  float2 e0,e1,e2,e3,o0,o1,o2,o3;
  dft4v<INV>(a[0],a[2],a[4],a[6],e0,e1,e2,e3);
  dft4v<INV>(a[1],a[3],a[5],a[7],o0,o1,o2,o3);
  const float C8 = 0.7071067811865476f;
  float2 p1 = INV ? cmulf(o1, make_float2(C8,C8))   : cmulf(o1, make_float2(C8,-C8));
  float2 p2 = INV ? make_float2(-o2.y,o2.x)         : make_float2(o2.y,-o2.x);
  float2 p3 = INV ? cmulf(o3, make_float2(-C8,C8))  : cmulf(o3, make_float2(-C8,-C8));
  b[0]=f2add(e0,o0); b[4]=f2sub(e0,o0);
  b[1]=f2add(e1,p1); b[5]=f2sub(e1,p1);
  b[2]=f2add(e2,p2); b[6]=f2sub(e2,p2);
  b[3]=f2add(e3,p3); b[7]=f2sub(e3,p3);
}

template<bool INV, int NS>
__device__ __forceinline__ void tw8(int jm, float2* w){
  float sn,cs; tw_sincos(((INV?2.f:-2.f)*jm)/(8*NS), &sn, &cs);
  w[0]=make_float2(cs,sn);
  w[1]=cmulf(w[0],w[0]);
  w[2]=cmulf(w[1],w[0]);
  w[3]=cmulf(w[1],w[1]);
  w[4]=cmulf(w[3],w[0]);
  w[5]=cmulf(w[2],w[2]);
  w[6]=cmulf(w[3],w[2]);
}

// ---- in-place stages (read -> sync -> write -> sync) ----
template<bool INV, int N, int NS>
__device__ __forceinline__ void row_r8_ip(float2* buf, int t){
  constexpr int T = N/8;
  const int jm = t & (NS-1);
  float2 a[8];
  #pragma unroll
  for (int k=0;k<8;k++) a[k]=buf[IX(t+k*T)];
  __syncthreads();
  if (NS>1){
    float2 w[7]; tw8<INV,NS>(jm,w);
    #pragma unroll
    for (int k=1;k<8;k++) a[k]=cmulf(a[k],w[k-1]);
  }
  float2 b[8]; dft8v<INV>(a,b);
  const int d=((t-jm)<<3)+jm;
  #pragma unroll
  for (int k=0;k<8;k++) buf[IX(d+k*NS)]=b[k];
  __syncthreads();
}
template<bool INV, int N>
__device__ __forceinline__ void row_r4_tail_ip(float2* buf, int t){
  constexpr int T=N/8;
  float2 v[2][4];
  #pragma unroll
  for (int q=0;q<2;q++){
    int j=t+q*T;
    v[q][0]=buf[IX(j)];       v[q][1]=buf[IX(j+N/4)];
    v[q][2]=buf[IX(j+N/2)];   v[q][3]=buf[IX(j+3*(N/4))];
  }
  __syncthreads();
  #pragma unroll
  for (int q=0;q<2;q++){
    int j=t+q*T;
    float sn,cs; tw_sincos(((INV?2.f:-2.f)*j)/N,&sn,&cs);
    float2 w1=make_float2(cs,sn),w2=cmulf(w1,w1),w3=cmulf(w2,w1);
    float2 y0,y1,y2,y3;
    dft4v<INV>(v[q][0],cmulf(v[q][1],w1),cmulf(v[q][2],w2),cmulf(v[q][3],w3),y0,y1,y2,y3);
    buf[IX(j)]=y0; buf[IX(j+N/4)]=y1; buf[IX(j+N/2)]=y2; buf[IX(j+3*(N/4))]=y3;
  }
  __syncthreads();
}
template<bool INV, int N>
__device__ __forceinline__ void row_r2_tail_ip(float2* buf, int t){
  constexpr int T=N/8;
  float2 v0[4], v1[4];
  #pragma unroll
  for (int q=0;q<4;q++){
    int j=t+q*T;
    v0[q]=buf[IX(j)]; v1[q]=buf[IX(j+N/2)];
  }
  __syncthreads();
  #pragma unroll
  for (int q=0;q<4;q++){
    int j=t+q*T;
    float sn,cs; tw_sincos(((INV?2.f:-2.f)*j)/N,&sn,&cs);
    float2 vw=cmulf(v1[q],make_float2(cs,sn));
    buf[IX(j)]    =f2add(v0[q],vw);
    buf[IX(j+N/2)]=f2sub(v0[q],vw);
  }
  __syncthreads();
}

// ---------------- row kernels (single smem buffer) ----------------
template<int N, bool INV, int R>
__global__ void fft8_rows(float2* __restrict__ ga, float2* __restrict__ gb){
  constexpr int T = N/8;
  constexpr int PAD = N + N/16 + 2;
  __shared__ float2 sh[R][PAD];
  const int t = threadIdx.x, rr = threadIdx.y;
  float2* g = blockIdx.z ? gb : ga;
  float2* base = g + ((size_t)blockIdx.y * N + blockIdx.x*R + rr) * N;
  float2* buf = sh[rr];
  {
    float2 a[8], b[8];
    #pragma unroll
    for (int k=0;k<8;k++) a[k]=base[t+k*T];
    dft8v<INV>(a,b);
    const int d=t<<3;
    #pragma unroll
    for (int k=0;k<8;k++) buf[IX(d+k)]=b[k];
  }
  __syncthreads();
  row_r8_ip<INV,N,8>(buf,t);
  if (N==512)      row_r8_ip<INV,N,64>(buf,t);
  else if (N==256) row_r4_tail_ip<INV,N>(buf,t);
  else             row_r2_tail_ip<INV,N>(buf,t);
  const float sc = INV ? 1.0f/N : 1.0f;
  #pragma unroll
  for (int k=0;k<8;k++){
    float2 v = buf[IX(t+k*T)];
    base[t+k*T] = make_float2(v.x*sc, v.y*sc);
  }
}

// DIR row pass from compact real (N/2 x N/2), zero-padded. Writes grid rows < N/2.
template<int N, int R>
__global__ void fft8_rows_dir_real(float2* __restrict__ g, const float* __restrict__ xr){
  constexpr int T = N/8;
  constexpr int PAD = N + N/16 + 2;
  __shared__ float2 sh[R][PAD];
  const int t = threadIdx.x, rr = threadIdx.y;
  const int y = blockIdx.x*R + rr, b = blockIdx.y;
  const float* row = xr + ((size_t)b*(N/2) + y)*(N/2);
  float2* base = g + ((size_t)b * N + y) * N;
  float2* buf = sh[rr];
  {
    float2 a[8], bb[8];
    #pragma unroll
    for (int k=0;k<4;k++) a[k]=make_float2(row[t+k*T],0.f);
    #pragma unroll
    for (int k=4;k<8;k++) a[k]=make_float2(0.f,0.f);
    dft8v<false>(a,bb);
    const int d=t<<3;
    #pragma unroll
    for (int k=0;k<8;k++) buf[IX(d+k)]=bb[k];
  }
  __syncthreads();
  row_r8_ip<false,N,8>(buf,t);
  if (N==512)      row_r8_ip<false,N,64>(buf,t);
  else if (N==256) row_r4_tail_ip<false,N>(buf,t);
  else             row_r2_tail_ip<false,N>(buf,t);
  #pragma unroll
  for (int k=0;k<8;k++) base[t+k*T] = buf[IX(t+k*T)];
}

// ---------------- column kernels (single buffer, one column per thread) ------
template<bool INV, int N, int NS, int PAD>
__device__ __forceinline__ void col_r8_ip(float2 (*sh)[PAD], int t, int cc){
  constexpr int T = N/8;
  const int jm = t & (NS-1);
  float2 a[8];
  #pragma unroll
  for (int k=0;k<8;k++) a[k]=sh[cc][IX(t+k*T)];
  __syncthreads();
  if (NS>1){
    float2 w[7]; tw8<INV,NS>(jm,w);
    #pragma unroll
    for (int k=1;k<8;k++) a[k]=cmulf(a[k],w[k-1]);
  }
  float2 b[8]; dft8v<INV>(a,b);
  const int d=((t-jm)<<3)+jm;
  #pragma unroll
  for (int k=0;k<8;k++) sh[cc][IX(d+k*NS)]=b[k];
  __syncthreads();
}
template<bool INV, int N, int PAD>
__device__ __forceinline__ void col_r4_tail_ip(float2 (*sh)[PAD], int t, int cc){
  constexpr int T=N/8;
  float2 v[2][4];
  #pragma unroll
  for (int q=0;q<2;q++){
    int j=t+q*T;
    v[q][0]=sh[cc][IX(j)];       v[q][1]=sh[cc][IX(j+N/4)];
    v[q][2]=sh[cc][IX(j+N/2)];   v[q][3]=sh[cc][IX(j+3*(N/4))];
  }
  __syncthreads();
  #pragma unroll
  for (int q=0;q<2;q++){
    int j=t+q*T;
    float sn,cs; tw_sincos(((INV?2.f:-2.f)*j)/N,&sn,&cs);
    float2 w1=make_float2(cs,sn),w2=cmulf(w1,w1),w3=cmulf(w2,w1);
    float2 y0,y1,y2,y3;
    dft4v<INV>(v[q][0],cmulf(v[q][1],w1),cmulf(v[q][2],w2),cmulf(v[q][3],w3),y0,y1,y2,y3);
    sh[cc][IX(j)]=y0; sh[cc][IX(j+N/4)]=y1; sh[cc][IX(j+N/2)]=y2; sh[cc][IX(j+3*(N/4))]=y3;
  }
  __syncthreads();
}
template<bool INV, int N, int PAD>
__device__ __forceinline__ void col_r2_tail_ip(float2 (*sh)[PAD], int t, int cc){
  constexpr int T=N/8;
  float2 v0[4], v1[4];
  #pragma unroll
  for (int q=0;q<4;q++){
    int j=t+q*T;
    v0[q]=sh[cc][IX(j)]; v1[q]=sh[cc][IX(j+N/2)];
  }
  __syncthreads();
  #pragma unroll
  for (int q=0;q<4;q++){
    int j=t+q*T;
    float sn,cs; tw_sincos(((INV?2.f:-2.f)*j)/N,&sn,&cs);
    float2 vw=cmulf(v1[q],make_float2(cs,sn));
    sh[cc][IX(j)]    =f2add(v0[q],vw);
    sh[cc][IX(j+N/2)]=f2sub(v0[q],vw);
  }
  __syncthreads();
}

// ADJ col pass (inverse), pruned cols<N/2; Re of rows<N/2 to compact buffer.
template<int N, int TC>
__global__ void fft8_cols_adj_real(const float2* __restrict__ ga, float* __restrict__ da,
                                   const float2* __restrict__ gb, float* __restrict__ db2,
                                   int imgStride){
  constexpr int PAD = N + N/16 + 2;
  constexpr int T = N/8;
  constexpr int NT = T*TC;
  __shared__ float2 sh[TC][PAD];
  const int t = threadIdx.x, cc = threadIdx.y;
  const int tid = cc*T + t;
  const float2* g = blockIdx.z ? gb : ga;
  float* dstp = blockIdx.z ? db2 : da;
  const float2* base = g + (size_t)blockIdx.y * N * N + blockIdx.x * TC;
  float* db = dstp + (size_t)blockIdx.y * imgStride + blockIdx.x * TC;
  for (int i=tid; i<N*TC; i+=NT){
    int r=i/TC, c2=i&(TC-1);
    sh[c2][IX(r)] = base[(size_t)r*N + c2];
  }
  __syncthreads();
  col_r8_ip<true,N,1,PAD>(sh,t,cc);
  col_r8_ip<true,N,8,PAD>(sh,t,cc);
  if (N==512)      col_r8_ip<true,N,64,PAD>(sh,t,cc);
  else if (N==256) col_r4_tail_ip<true,N,PAD>(sh,t,cc);
  else             col_r2_tail_ip<true,N,PAD>(sh,t,cc);
  const float sc = 1.0f/N;
  for (int i=tid; i<(N/2)*TC; i+=NT){
    int r=i/TC, c2=i&(TC-1);
    db[(size_t)r*(N/2) + c2] = sh[c2][IX(r)].x * sc;
  }
}

// DIR col pass (forward): loads only rows < N/2 (rest zero via stage0), full store.
template<int N, int TC>
__global__ void fft8_cols_dir(float2* __restrict__ g){
  constexpr int PAD = N + N/16 + 2;
  constexpr int T = N/8;
  constexpr int NT = T*TC;
  __shared__ float2 sh[TC][PAD];
  const int t = threadIdx.x, cc = threadIdx.y;
  const int tid = cc*T + t;
  float2* base = g + (size_t)blockIdx.y * N * N + blockIdx.x * TC;
  for (int i=tid; i<(N/2)*TC; i+=NT){
    int r=i/TC, c2=i&(TC-1);
    sh[c2][IX(r)] = base[(size_t)r*N + c2];
  }
  __syncthreads();
  {
    float2 a[8], b[8];
    #pragma unroll
    for (int k=0;k<4;k++) a[k]=sh[cc][IX(t+k*T)];
    #pragma unroll
    for (int k=4;k<8;k++) a[k]=make_float2(0.f,0.f);
    __syncthreads();
    dft8v<false>(a,b);
    const int d=t<<3;
    #pragma unroll
    for (int k=0;k<8;k++) sh[cc][IX(d+k)]=b[k];
  }
  __syncthreads();
  col_r8_ip<false,N,8,PAD>(sh,t,cc);
  if (N==512)      col_r8_ip<false,N,64,PAD>(sh,t,cc);
  else if (N==256) col_r4_tail_ip<false,N,PAD>(sh,t,cc);
  else             col_r2_tail_ip<false,N,PAD>(sh,t,cc);
  for (int i=tid; i<N*TC; i+=NT){
    int r=i/TC, c2=i&(TC-1);
    base[(size_t)r*N + c2] = sh[c2][IX(r)];
  }
}

// ---------------- NUFFT pieces ----------------
__global__ void k_scatter_vis(float2* __restrict__ grid, const float* __restrict__ vr,
                              const float* __restrict__ vi, const float* __restrict__ w,
                              const int* __restrict__ idx){
  int i = blockIdx.x*blockDim.x+threadIdx.x;
  if (i >= BATCH*MVIS) return;
  int b=i/MVIS, k=i-b*MVIS;
  float wv=w[k];
  red2(&grid[b*512*512+idx[k]], vr[i]*wv, vi[i]*wv);
}

__global__ void k_gather_m0(const float2* __restrict__ grid, const int* __restrict__ idx,
                            const float* __restrict__ w, float2* __restrict__ m0,
                            float2* __restrict__ sub0){
  int i = blockIdx.x*blockDim.x+threadIdx.x;
  if (i >= BATCH*MVIS) return;
  int b=i/MVIS, k=i-b*MVIS;
  float2 v = grid[b*512*512+idx[k]];
  m0[i]=v; float wv=w[k];
  sub0[i]=make_float2(v.x*wv, v.y*wv);
}

__global__ void k_scatter_sel(float2* __restrict__ grid, const float2* __restrict__ src,
                              const int* __restrict__ sel, const int* __restrict__ idx,
                              int n, int srcStride, int gridSize){
  int i = blockIdx.x*blockDim.x+threadIdx.x;
  if (i >= BATCH*n) return;
  int b=i/n, j=i-b*n;
  float2 v = src[(size_t)b*srcStride + sel[j]];
  red2(&grid[b*gridSize + idx[j]], v.x, v.y);
}

__global__ void k_gather(const float2* __restrict__ grid, const int* __restrict__ idx,
                         float2* __restrict__ dst, int n, int dstStride, int gridSize){
  int i = blockIdx.x*blockDim.x+threadIdx.x;
  if (i >= BATCH*n) return;
  int b=i/n, j=i-b*n;
  dst[(size_t)b*dstStride + j] = grid[b*gridSize + idx[j]];
}

__global__ void k_set_sel(float2* __restrict__ dstVec, const int* __restrict__ sel,
                          const float2* __restrict__ grid, const int* __restrict__ idx,
                          int n, int dstStride, int gridSize){
  int i = blockIdx.x*blockDim.x+threadIdx.x;
  if (i >= BATCH*n) return;
  int b=i/n, j=i-b*n;
  dstVec[(size_t)b*dstStride + sel[j]] = grid[b*gridSize + idx[j]];
}

__global__ void k_scatterE(float2* __restrict__ gA, float2* __restrict__ gB,
                           const float2* __restrict__ m1, const float2* __restrict__ sub0,
                           const int* __restrict__ sel1, const int* __restrict__ idx1, int n1){
  int i = blockIdx.x*blockDim.x+threadIdx.x;
  if (i >= BATCH*n1) return;
  int b=i/n1, j=i-b*n1;
  float2 v = m1[(size_t)b*n1 + j];
  float2 s = sub0[(size_t)b*MVIS + sel1[j]];
  int gi = b*65536 + idx1[j];
  red2(&gA[gi], v.x, v.y);
  red2(&gB[gi], v.x-s.x, v.y-s.y);
}

__global__ void k_scatterG(float2* __restrict__ gA, float2* __restrict__ gB,
                           const float2* __restrict__ m0, const float2* __restrict__ sub0,
                           const int* __restrict__ idx0){
  int i = blockIdx.x*blockDim.x+threadIdx.x;
  if (i >= BATCH*MVIS) return;
  int b=i/MVIS, k=i-b*MVIS;
  float2 v=m0[i], s=sub0[i];
  int gi = b*262144 + idx0[k];
  red2(&gA[gi], v.x, v.y);
  red2(&gB[gi], v.x-s.x, v.y-s.y);
}

// ---------------- fused conv block: conv1+bn+conv2+bn+conv3+sigmoid ----------
// Dynamic smem layout (floats): sc[2*20*20] | shh[F*18*18] | sw1[18F] | sw2[9FF] |
//                               sb1,sg1,sbe1,sb2,sg2,sbe2,sw3 [F each]
template<int F, int H>
__global__ void __launch_bounds__(256) conv123_k(
    const float* __restrict__ cin,
    const float* __restrict__ W1, const float* __restrict__ b1,
    const float* __restrict__ g1, const float* __restrict__ be1,
    const float* __restrict__ W2, const float* __restrict__ b2,
    const float* __restrict__ g2, const float* __restrict__ be2,
    const float* __restrict__ W3, const float* __restrict__ b3,
    float* __restrict__ outp){
  extern __shared__ float smem[];
  float* sc  = smem;                  // 2*20*20 = 800
  float* shh = sc + 800;              // F*324
  float* sw1 = shh + F*324;           // 18F
  float* sw2 = sw1 + 18*F;            // 9FF
  float* sb1 = sw2 + 9*F*F;
  float* sg1 = sb1 + F;
  float* sbe1= sg1 + F;
  float* sb2 = sbe1+ F;
  float* sg2 = sb2 + F;
  float* sbe2= sg2 + F;
  float* sw3 = sbe2+ F;

  const int tx=threadIdx.x, ty=threadIdx.y, tid=ty*16+tx;
  const int b=blockIdx.z, x0=blockIdx.x*16, y0=blockIdx.y*16;

  for (int i=tid; i<18*F; i+=256) sw1[i]=W1[i];
  for (int i=tid; i<9*F*F; i+=256){
    int oc=i%F, r=i/F, tap=r%9, ic=r/9;
    sw2[i] = W2[(tap*F+ic)*F+oc];
  }
  for (int i=tid; i<F; i+=256){
    sb1[i]=b1[i]; sg1[i]=g1[i]*RBN; sbe1[i]=be1[i];
    sb2[i]=b2[i]; sg2[i]=g2[i]*RBN; sbe2[i]=be2[i]; sw3[i]=W3[i];
  }
  // cin tiles: 20x20 halo, sc[c][yy][xx] holds (y0+yy-2, x0+xx-2)
  const float* cb = cin + (size_t)b*2*H*H;
  for (int c=0;c<2;c++)
    for (int i=tid;i<20*20;i+=256){
      int yy=i/20, xx=i-yy*20;
      int gy=y0+yy-2, gx=x0+xx-2;
      sc[c*400+i] = (gy>=0&&gy<H&&gx>=0&&gx<H) ? cb[c*H*H + gy*H + gx] : 0.f;
    }
  __syncthreads();

  // conv1 phase: compute h on 18x18 halo (h coords hy,hx; global y = y0+hy-1)
  for (int i=tid; i<18*18; i+=256){
    int hy=i/18, hx=i-hy*18;
    int yh=y0+hy-1, xh=x0+hx-1;
    bool inb = (yh>=0 && yh<H && xh>=0 && xh<H);
    if (inb){
      unsigned long long acc[F/2];
      #pragma unroll
      for (int o2=0;o2<F/2;o2++) acc[o2]=pack2(sb1[2*o2], sb1[2*o2+1]);
      #pragma unroll
      for (int ky=0;ky<3;ky++)
        #pragma unroll
        for (int kx=0;kx<3;kx++)
          #pragma unroll
          for (int c=0;c<2;c++){
            unsigned long long vv = dup2(sc[c*400 + (hy+ky)*20 + (hx+kx)]);
            const float* wt = sw1 + ((ky*3+kx)*2+c)*F;
            #pragma unroll
            for (int o2=0;o2<F/2;o2++)
              fma2(acc[o2], vv, *reinterpret_cast<const unsigned long long*>(wt + 2*o2), acc[o2]);
          }
      #pragma unroll
      for (int o2=0;o2<F/2;o2++){
        float2 a = unpack2(acc[o2]);
        shh[(2*o2  )*324 + i] = fmaf(fmaxf(a.x,0.f), sg1[2*o2  ], sbe1[2*o2  ]);
        shh[(2*o2+1)*324 + i] = fmaf(fmaxf(a.y,0.f), sg1[2*o2+1], sbe1[2*o2+1]);
      }
    } else {
      #pragma unroll
      for (int o=0;o<F;o++) shh[o*324 + i] = 0.f;
    }
  }
  __syncthreads();

  // conv2 mainloop (no barriers: shh read-only now) + conv3 epilogue
  unsigned long long acc2[F/2];
  #pragma unroll
  for (int o2=0;o2<F/2;o2++) acc2[o2]=pack2(sb2[2*o2], sb2[2*o2+1]);
  for (int ic=0; ic<F; ic++){
    const float* hti = shh + ic*324;
    const float* wi  = sw2 + ic*9*F;
    #pragma unroll
    for (int ky=0;ky<3;ky++)
      #pragma unroll
      for (int kx=0;kx<3;kx++){
        unsigned long long vv = dup2(hti[(ty+ky)*18 + (tx+kx)]);
        const float* wt = wi + (ky*3+kx)*F;
        #pragma unroll
        for (int o2=0;o2<F/2;o2++)
          fma2(acc2[o2], vv, *reinterpret_cast<const unsigned long long*>(wt + 2*o2), acc2[o2]);
      }
  }
  float s = b3[0];
  #pragma unroll
  for (int o2=0;o2<F/2;o2++){
    float2 a = unpack2(acc2[o2]);
    s = fmaf(fmaf(fmaxf(a.x,0.f), sg2[2*o2  ], sbe2[2*o2  ]), sw3[2*o2  ], s);
    s = fmaf(fmaf(fmaxf(a.y,0.f), sg2[2*o2+1], sbe2[2*o2+1]), sw3[2*o2+1], s);
  }
  outp[(size_t)b*H*H + (size_t)(y0+ty)*H + (x0+tx)] = 1.f/(1.f+__expf(-s));
}

// ---------------- launch ----------------
extern "C" void kernel_launch(void* const* d_in, const int* in_sizes, int n_in,
                              void* d_out, int out_size){
  const float* vr = (const float*)d_in[0];
  const float* vi = (const float*)d_in[1];
  const float* w  = (const float*)d_in[2];
  const float *c0w1=(const float*)d_in[3],  *c0b1=(const float*)d_in[4],
              *c0g1=(const float*)d_in[5],  *c0be1=(const float*)d_in[6],
              *c0w2=(const float*)d_in[7],  *c0b2=(const float*)d_in[8],
              *c0g2=(const float*)d_in[9],  *c0be2=(const float*)d_in[10],
              *c0w3=(const float*)d_in[11], *c0b3=(const float*)d_in[12];
  const float *c1w1=(const float*)d_in[13], *c1b1=(const float*)d_in[14],
              *c1g1=(const float*)d_in[15], *c1be1=(const float*)d_in[16],
              *c1w2=(const float*)d_in[17], *c1b2=(const float*)d_in[18],
              *c1g2=(const float*)d_in[19], *c1be2=(const float*)d_in[20],
              *c1w3=(const float*)d_in[21], *c1b3=(const float*)d_in[22];
  const int* idx0=(const int*)d_in[23];
  const int* idx1=(const int*)d_in[24];
  const int* idx2=(const int*)d_in[25];
  const int* sel1=(const int*)d_in[26];
  const int* sel2=(const int*)d_in[27];
  const int n1 = in_sizes[24], n2 = in_sizes[25];
  float* out = (float*)d_out;

  float2 *gA,*gB,*m0,*m1,*sub0; float *cin,*xc,*q0,*q1,*q2;
  cudaGetSymbolAddress((void**)&gA,   g_grids);
  gB = gA + (size_t)BATCH*512*512;
  cudaGetSymbolAddress((void**)&m0,   g_m0);
  cudaGetSymbolAddress((void**)&m1,   g_m1);
  cudaGetSymbolAddress((void**)&sub0, g_sub0);
  cudaGetSymbolAddress((void**)&cin,  g_cin);
  cudaGetSymbolAddress((void**)&xc,   g_xc);
  cudaGetSymbolAddress((void**)&q0,   g_q0);
  cudaGetSymbolAddress((void**)&q1,   g_q1);
  cudaGetSymbolAddress((void**)&q2,   g_q2);

  const int SM0 = (800 + 32*324 + 18*32 + 9*32*32 + 7*32)*4;   // 84736 B
  const int SM1 = (800 + 16*324 + 18*16 + 9*16*16 + 7*16)*4;   // 34752 B
  cudaFuncSetAttribute(conv123_k<32,128>, cudaFuncAttributeMaxDynamicSharedMemorySize, SM0);
  cudaFuncSetAttribute(conv123_k<16,256>, cudaFuncAttributeMaxDynamicSharedMemorySize, SM1);

  const int TPB=256;
  // A: adj0 of vis*w -> q0 (256x256 real quadrant)
  cudaMemsetAsync(gA, 0, (size_t)BATCH*262144*sizeof(float2), 0);
  k_scatter_vis<<<CDIV(BATCH*MVIS,TPB),TPB>>>(gA, vr, vi, w, idx0);
  fft8_rows<512,true,4><<<dim3(128,BATCH,1),dim3(64,4)>>>(gA, gA);
  fft8_cols_adj_real<512,4><<<dim3(64,BATCH,1),dim3(64,4)>>>(gA, q0, gA, q0, 256*256);
  // B: dir0 from q0 -> m0, sub0
  fft8_rows_dir_real<512,4><<<dim3(64,BATCH),dim3(64,4)>>>(gA, q0);
  fft8_cols_dir<512,4><<<dim3(128,BATCH),dim3(64,4)>>>(gA);
  k_gather_m0<<<CDIV(BATCH*MVIS,TPB),TPB>>>(gA, idx0, w, m0, sub0);
  // C: adj1 of m0[sel1] -> q1 (128x128)
  cudaMemsetAsync(gB, 0, (size_t)BATCH*65536*sizeof(float2), 0);
  k_scatter_sel<<<CDIV(BATCH*n1,TPB),TPB>>>(gB, m0, sel1, idx1, n1, MVIS, 65536);
  fft8_rows<256,true,8><<<dim3(32,BATCH,1),dim3(32,8)>>>(gB, gB);
  fft8_cols_adj_real<256,8><<<dim3(16,BATCH,1),dim3(32,8)>>>(gB, q1, gB, q1, 128*128);
  // D: dir1 from q1 -> m1
  fft8_rows_dir_real<256,8><<<dim3(16,BATCH),dim3(32,8)>>>(gB, q1);
  fft8_cols_dir<256,8><<<dim3(32,BATCH),dim3(32,8)>>>(gB);
  k_gather<<<CDIV(BATCH*n1,TPB),TPB>>>(gB, idx1, m1, n1, n1, 65536);
  // E: adj2 of m1[sel2] -> q2 (64x64)
  cudaMemsetAsync(gA, 0, (size_t)BATCH*16384*sizeof(float2), 0);
  k_scatter_sel<<<CDIV(BATCH*n2,TPB),TPB>>>(gA, m1, sel2, idx2, n2, n1, 16384);
  fft8_rows<128,true,16><<<dim3(8,BATCH,1),dim3(16,16)>>>(gA, gA);
  fft8_cols_adj_real<128,8><<<dim3(8,BATCH,1),dim3(16,8)>>>(gA, q2, gA, q2, 64*64);
  // F: dir2 from q2 -> meas; m1 becomes full1
  fft8_rows_dir_real<128,16><<<dim3(4,BATCH),dim3(16,16)>>>(gA, q2);
  fft8_cols_dir<128,8><<<dim3(16,BATCH),dim3(16,8)>>>(gA);
  k_set_sel<<<CDIV(BATCH*n2,TPB),TPB>>>(m1, sel2, gA, idx2, n2, n1, 16384);
  // G: two adj1 (full1, full1 - sub1) -> cin channels directly (merged via z)
  cudaMemsetAsync(gA, 0, (size_t)BATCH*65536*sizeof(float2), 0);
  cudaMemsetAsync(gB, 0, (size_t)BATCH*65536*sizeof(float2), 0);
  k_scatterE<<<CDIV(BATCH*n1,TPB),TPB>>>(gA, gB, m1, sub0, sel1, idx1, n1);
  fft8_rows<256,true,8><<<dim3(32,BATCH,2),dim3(32,8)>>>(gA, gB);
  fft8_cols_adj_real<256,8><<<dim3(16,BATCH,2),dim3(32,8)>>>(gA, cin, gB, cin + 128*128, 2*128*128);
  // H: fused conv block p0 (F=32 @128) -> xc
  conv123_k<32,128><<<dim3(8,8,BATCH),dim3(16,16),SM0>>>(
      cin, c0w1, c0b1, c0g1, c0be1, c0w2, c0b2, c0g2, c0be2, c0w3, c0b3, xc);
  // I: dir1 of xc; m0 becomes full0
  fft8_rows_dir_real<256,8><<<dim3(16,BATCH),dim3(32,8)>>>(gA, xc);
  fft8_cols_dir<256,8><<<dim3(32,BATCH),dim3(32,8)>>>(gA);
  k_set_sel<<<CDIV(BATCH*n1,TPB),TPB>>>(m0, sel1, gA, idx1, n1, MVIS, 65536);
  // J: two adj0 (full0, full0 - sub0) -> cin (gA,gB contiguous: one memset)
  cudaMemsetAsync(gA, 0, (size_t)2*BATCH*262144*sizeof(float2), 0);
  k_scatterG<<<CDIV(BATCH*MVIS,TPB),TPB>>>(gA, gB, m0, sub0, idx0);
  fft8_rows<512,true,4><<<dim3(128,BATCH,2),dim3(64,4)>>>(gA, gB);
  fft8_cols_adj_real<512,4><<<dim3(64,BATCH,2),dim3(64,4)>>>(gA, cin, gB, cin + 256*256, 2*256*256);
  // K: fused conv block p1 (F=16 @256) -> out
  conv123_k<16,256><<<dim3(16,16,BATCH),dim3(16,16),SM1>>>(
      cin, c1w1, c1b1, c1g1, c1be1, c1w2, c1b2, c1g2, c1be2, c1w3, c1b3, out);
}